// round 12
// baseline (speedup 1.0000x reference)
#include <cuda_runtime.h>
#include <math.h>

// BalancedAveragedHausdorffLoss, single fused kernel, v8.
// 128 blocks = (item, quarter), 1024 threads. Each block computes BOTH
// EDT directions (pred->target and target->pred): inputs loaded once,
// two ballot row-mask sets, two h^2 arrays, and a single per-pixel
// early-exit vote loop advancing both distances. Finalize in last block.

#define ITEMS 32
#define Wdim  64
#define HW    4096
#define GINF  127   // GINF^2 = 16129

#define NT    1024
#define NWARP 32

__device__ float        g_t1[4 * ITEMS];   // term1 partial [item*4 + q]
__device__ float        g_t2[4 * ITEMS];   // term2 partial
__device__ int          g_ct[4 * ITEMS];   // n_t partial
__device__ int          g_cp[4 * ITEMS];   // n_p partial
__device__ unsigned int g_done;            // 0 at start; reset by last block

// nearest-set-bit distance from position p in 64-bit mask M (GINF if none)
__device__ __forceinline__ int bitdist(unsigned long long M, int p) {
    unsigned long long U = M >> p;
    unsigned long long V = M << (63 - p);
    int dDown = U ? (__ffsll((long long)U) - 1) : GINF;
    int dUp   = V ? __clzll((long long)V)      : GINF;
    return min(dDown, dUp);
}

__global__ __launch_bounds__(NT)
void bahl_fused_kernel(const float* __restrict__ pred,
                       const float* __restrict__ target,
                       float* __restrict__ out)
{
    __shared__ unsigned long long prmask[Wdim];  // pred-mask bits per row
    __shared__ unsigned long long trmask[Wdim];  // target-mask bits per row
    __shared__ int   h2t[HW];                    // squared horiz dist to target mask
    __shared__ int   h2p[HW];                    // squared horiz dist to pred mask
    __shared__ float s1[NWARP], s2[NWARP];
    __shared__ int   sct[NWARP], scp[NWARP];
    __shared__ int   sIsLast;

    const int bi      = blockIdx.x;
    const int item    = bi >> 2;
    const int quarter = bi & 3;
    const int tid     = threadIdx.x;

    const float* pb = pred   + item * HW;
    const float* tb = target + item * HW;
    const float THR = 0.30001f;

    // --- Load both images once; build both row-mask sets via ballot. ----
    // Thread's own phase-2 pixel (quarter*1024 + tid) is the k==quarter iter.
    unsigned pmbit = 0, tmbit = 0;
    #pragma unroll
    for (int k = 0; k < 4; k++) {
        const int pix = tid + k * NT;
        float pv = pb[pix];
        float tv = tb[pix];
        bool pmb = (fabsf(pv - 1.0f) <= THR);
        bool tmb = (tv != 0.0f);
        unsigned pbal = __ballot_sync(0xffffffffu, pmb);
        unsigned tbal = __ballot_sync(0xffffffffu, tmb);
        if ((tid & 31) == 0) {
            ((unsigned*)prmask)[pix >> 5] = pbal;
            ((unsigned*)trmask)[pix >> 5] = tbal;
        }
        if (k == quarter) { pmbit = pmb ? 1u : 0u; tmbit = tmb ? 1u : 0u; }
    }
    __syncthreads();   // masks complete

    // --- Phase 1: squared horizontal distances for BOTH masks -----------
    #pragma unroll
    for (int k = 0; k < 4; k++) {
        const int idx = tid + k * NT;
        const int x = idx >> 6, y = idx & 63;
        int ht = bitdist(trmask[x], y);
        int hp = bitdist(prmask[x], y);
        h2t[idx] = ht * ht;
        h2p[idx] = hp * hp;
    }
    __syncthreads();

    // --- Phase 2: one pixel per thread, both distances, one vote loop ---
    const int pix = quarter * NT + tid;
    const int x = pix >> 6;
    const int y = pix & 63;
    int dt = h2t[pix];            // dist^2 to target mask (r = 0)
    int dp = h2p[pix];            // dist^2 to pred mask
    #pragma unroll 1
    for (int r = 1; r < Wdim; r++) {
        const int rr = r * r;
        if (!__any_sync(0xffffffffu, rr < max(dt, dp))) break;
        const int xu = x - r, xd = x + r;
        if (xu >= 0) {
            const int off = xu * Wdim + y;
            dt = min(dt, rr + h2t[off]);
            dp = min(dp, rr + h2p[off]);
        }
        if (xd < Wdim) {
            const int off = xd * Wdim + y;
            dt = min(dt, rr + h2t[off]);
            dp = min(dp, rr + h2p[off]);
        }
    }
    float a1 = pmbit ? sqrtf((float)dt) : 0.0f;   // term1: pred px -> target
    float a2 = tmbit ? sqrtf((float)dp) : 0.0f;   // term2: target px -> pred
    int   cp = (int)pmbit, ct = (int)tmbit;

    // --- Block reduction (32 warps) --------------------------------------
    #pragma unroll
    for (int o = 16; o > 0; o >>= 1) {
        a1 += __shfl_xor_sync(0xffffffffu, a1, o);
        a2 += __shfl_xor_sync(0xffffffffu, a2, o);
        ct += __shfl_xor_sync(0xffffffffu, ct, o);
        cp += __shfl_xor_sync(0xffffffffu, cp, o);
    }
    const int wid = tid >> 5, lid = tid & 31;
    if (lid == 0) { s1[wid] = a1; s2[wid] = a2; sct[wid] = ct; scp[wid] = cp; }
    __syncthreads();

    if (tid == 0) {
        float t1 = 0.0f, t2 = 0.0f; int tC = 0, pC = 0;
        #pragma unroll
        for (int w = 0; w < NWARP; w++) {
            t1 += s1[w]; t2 += s2[w]; tC += sct[w]; pC += scp[w];
        }
        g_t1[bi] = t1; g_t2[bi] = t2; g_ct[bi] = tC; g_cp[bi] = pC;
        __threadfence();
        unsigned old = atomicAdd(&g_done, 1u);
        sIsLast = (old == 4 * ITEMS - 1) ? 1 : 0;
    }
    __syncthreads();

    // --- Parallel finalize in last block: lane i handles item i ----------
    if (sIsLast && tid < 32) {
        __threadfence();
        volatile float* v1 = g_t1;
        volatile float* v2 = g_t2;
        volatile int*   vt = g_ct;
        volatile int*   vp = g_cp;
        const int i = tid;
        float t1 = v1[4*i] + v1[4*i+1] + v1[4*i+2] + v1[4*i+3];
        float t2 = v2[4*i] + v2[4*i+1] + v2[4*i+2] + v2[4*i+3];
        int   nt = vt[4*i] + vt[4*i+1] + vt[4*i+2] + vt[4*i+3];
        int   np = vp[4*i] + vp[4*i+1] + vp[4*i+2] + vp[4*i+3];
        float v = (nt > 0 && np > 0) ? (t1 + t2) / (2.0f * (float)nt) : 0.0f;
        #pragma unroll
        for (int o = 16; o > 0; o >>= 1)
            v += __shfl_xor_sync(0xffffffffu, v, o);
        if (tid == 0) {
            out[0] = v / (float)ITEMS;
            __threadfence();
            g_done = 0;                   // reset for next graph replay
        }
    }
}

extern "C" void kernel_launch(void* const* d_in, const int* in_sizes, int n_in,
                              void* d_out, int out_size)
{
    const float* pred   = (const float*)d_in[0];
    const float* target = (const float*)d_in[1];
    float* out = (float*)d_out;
    (void)in_sizes; (void)n_in; (void)out_size;

    bahl_fused_kernel<<<4 * ITEMS, NT>>>(pred, target, out);
}

// round 13
// speedup vs baseline: 1.0027x; 1.0027x over previous
#include <cuda_runtime.h>
#include <math.h>

// BalancedAveragedHausdorffLoss, single fused kernel, v8.
// 128 blocks = (item, quarter), 1024 threads. Each block computes BOTH
// EDT directions (pred->target and target->pred): inputs loaded once,
// two ballot row-mask sets, two h^2 arrays, and a single per-pixel
// early-exit vote loop advancing both distances. Finalize in last block.

#define ITEMS 32
#define Wdim  64
#define HW    4096
#define GINF  127   // GINF^2 = 16129

#define NT    1024
#define NWARP 32

__device__ float        g_t1[4 * ITEMS];   // term1 partial [item*4 + q]
__device__ float        g_t2[4 * ITEMS];   // term2 partial
__device__ int          g_ct[4 * ITEMS];   // n_t partial
__device__ int          g_cp[4 * ITEMS];   // n_p partial
__device__ unsigned int g_done;            // 0 at start; reset by last block

// nearest-set-bit distance from position p in 64-bit mask M (GINF if none)
__device__ __forceinline__ int bitdist(unsigned long long M, int p) {
    unsigned long long U = M >> p;
    unsigned long long V = M << (63 - p);
    int dDown = U ? (__ffsll((long long)U) - 1) : GINF;
    int dUp   = V ? __clzll((long long)V)      : GINF;
    return min(dDown, dUp);
}

__global__ __launch_bounds__(NT)
void bahl_fused_kernel(const float* __restrict__ pred,
                       const float* __restrict__ target,
                       float* __restrict__ out)
{
    __shared__ unsigned long long prmask[Wdim];  // pred-mask bits per row
    __shared__ unsigned long long trmask[Wdim];  // target-mask bits per row
    __shared__ int   h2t[HW];                    // squared horiz dist to target mask
    __shared__ int   h2p[HW];                    // squared horiz dist to pred mask
    __shared__ float s1[NWARP], s2[NWARP];
    __shared__ int   sct[NWARP], scp[NWARP];
    __shared__ int   sIsLast;

    const int bi      = blockIdx.x;
    const int item    = bi >> 2;
    const int quarter = bi & 3;
    const int tid     = threadIdx.x;

    const float* pb = pred   + item * HW;
    const float* tb = target + item * HW;
    const float THR = 0.30001f;

    // --- Load both images once; build both row-mask sets via ballot. ----
    // Thread's own phase-2 pixel (quarter*1024 + tid) is the k==quarter iter.
    unsigned pmbit = 0, tmbit = 0;
    #pragma unroll
    for (int k = 0; k < 4; k++) {
        const int pix = tid + k * NT;
        float pv = pb[pix];
        float tv = tb[pix];
        bool pmb = (fabsf(pv - 1.0f) <= THR);
        bool tmb = (tv != 0.0f);
        unsigned pbal = __ballot_sync(0xffffffffu, pmb);
        unsigned tbal = __ballot_sync(0xffffffffu, tmb);
        if ((tid & 31) == 0) {
            ((unsigned*)prmask)[pix >> 5] = pbal;
            ((unsigned*)trmask)[pix >> 5] = tbal;
        }
        if (k == quarter) { pmbit = pmb ? 1u : 0u; tmbit = tmb ? 1u : 0u; }
    }
    __syncthreads();   // masks complete

    // --- Phase 1: squared horizontal distances for BOTH masks -----------
    #pragma unroll
    for (int k = 0; k < 4; k++) {
        const int idx = tid + k * NT;
        const int x = idx >> 6, y = idx & 63;
        int ht = bitdist(trmask[x], y);
        int hp = bitdist(prmask[x], y);
        h2t[idx] = ht * ht;
        h2p[idx] = hp * hp;
    }
    __syncthreads();

    // --- Phase 2: one pixel per thread, both distances, one vote loop ---
    const int pix = quarter * NT + tid;
    const int x = pix >> 6;
    const int y = pix & 63;
    int dt = h2t[pix];            // dist^2 to target mask (r = 0)
    int dp = h2p[pix];            // dist^2 to pred mask
    #pragma unroll 1
    for (int r = 1; r < Wdim; r++) {
        const int rr = r * r;
        if (!__any_sync(0xffffffffu, rr < max(dt, dp))) break;
        const int xu = x - r, xd = x + r;
        if (xu >= 0) {
            const int off = xu * Wdim + y;
            dt = min(dt, rr + h2t[off]);
            dp = min(dp, rr + h2p[off]);
        }
        if (xd < Wdim) {
            const int off = xd * Wdim + y;
            dt = min(dt, rr + h2t[off]);
            dp = min(dp, rr + h2p[off]);
        }
    }
    float a1 = pmbit ? sqrtf((float)dt) : 0.0f;   // term1: pred px -> target
    float a2 = tmbit ? sqrtf((float)dp) : 0.0f;   // term2: target px -> pred
    int   cp = (int)pmbit, ct = (int)tmbit;

    // --- Block reduction (32 warps) --------------------------------------
    #pragma unroll
    for (int o = 16; o > 0; o >>= 1) {
        a1 += __shfl_xor_sync(0xffffffffu, a1, o);
        a2 += __shfl_xor_sync(0xffffffffu, a2, o);
        ct += __shfl_xor_sync(0xffffffffu, ct, o);
        cp += __shfl_xor_sync(0xffffffffu, cp, o);
    }
    const int wid = tid >> 5, lid = tid & 31;
    if (lid == 0) { s1[wid] = a1; s2[wid] = a2; sct[wid] = ct; scp[wid] = cp; }
    __syncthreads();

    if (tid == 0) {
        float t1 = 0.0f, t2 = 0.0f; int tC = 0, pC = 0;
        #pragma unroll
        for (int w = 0; w < NWARP; w++) {
            t1 += s1[w]; t2 += s2[w]; tC += sct[w]; pC += scp[w];
        }
        g_t1[bi] = t1; g_t2[bi] = t2; g_ct[bi] = tC; g_cp[bi] = pC;
        __threadfence();
        unsigned old = atomicAdd(&g_done, 1u);
        sIsLast = (old == 4 * ITEMS - 1) ? 1 : 0;
    }
    __syncthreads();

    // --- Parallel finalize in last block: lane i handles item i ----------
    if (sIsLast && tid < 32) {
        __threadfence();
        volatile float* v1 = g_t1;
        volatile float* v2 = g_t2;
        volatile int*   vt = g_ct;
        volatile int*   vp = g_cp;
        const int i = tid;
        float t1 = v1[4*i] + v1[4*i+1] + v1[4*i+2] + v1[4*i+3];
        float t2 = v2[4*i] + v2[4*i+1] + v2[4*i+2] + v2[4*i+3];
        int   nt = vt[4*i] + vt[4*i+1] + vt[4*i+2] + vt[4*i+3];
        int   np = vp[4*i] + vp[4*i+1] + vp[4*i+2] + vp[4*i+3];
        float v = (nt > 0 && np > 0) ? (t1 + t2) / (2.0f * (float)nt) : 0.0f;
        #pragma unroll
        for (int o = 16; o > 0; o >>= 1)
            v += __shfl_xor_sync(0xffffffffu, v, o);
        if (tid == 0) {
            out[0] = v / (float)ITEMS;
            __threadfence();
            g_done = 0;                   // reset for next graph replay
        }
    }
}

extern "C" void kernel_launch(void* const* d_in, const int* in_sizes, int n_in,
                              void* d_out, int out_size)
{
    const float* pred   = (const float*)d_in[0];
    const float* target = (const float*)d_in[1];
    float* out = (float*)d_out;
    (void)in_sizes; (void)n_in; (void)out_size;

    bahl_fused_kernel<<<4 * ITEMS, NT>>>(pred, target, out);
}

// round 14
// speedup vs baseline: 1.1134x; 1.1104x over previous
#include <cuda_runtime.h>
#include <math.h>

// BalancedAveragedHausdorffLoss, single fused kernel, v9.
// v8 body (128 blocks = (item, quarter), 1024 threads, both EDT directions
// per block) with skeleton cuts: vote-free unroll of r=1,2 in phase 2,
// REDUX count reductions, and a barrier-free last-block handoff
// (tid0 atomic -> warp-0 shfl broadcast instead of smem + syncthreads).

#define ITEMS 32
#define Wdim  64
#define HW    4096
#define GINF  127   // GINF^2 = 16129

#define NT    1024
#define NWARP 32

__device__ float        g_t1[4 * ITEMS];   // term1 partial [item*4 + q]
__device__ float        g_t2[4 * ITEMS];   // term2 partial
__device__ int          g_ct[4 * ITEMS];   // n_t partial
__device__ int          g_cp[4 * ITEMS];   // n_p partial
__device__ unsigned int g_done;            // 0 at start; reset by last block

// nearest-set-bit distance from position p in 64-bit mask M (GINF if none)
__device__ __forceinline__ int bitdist(unsigned long long M, int p) {
    unsigned long long U = M >> p;
    unsigned long long V = M << (63 - p);
    int dDown = U ? (__ffsll((long long)U) - 1) : GINF;
    int dUp   = V ? __clzll((long long)V)      : GINF;
    return min(dDown, dUp);
}

__global__ __launch_bounds__(NT)
void bahl_fused_kernel(const float* __restrict__ pred,
                       const float* __restrict__ target,
                       float* __restrict__ out)
{
    __shared__ unsigned long long prmask[Wdim];  // pred-mask bits per row
    __shared__ unsigned long long trmask[Wdim];  // target-mask bits per row
    __shared__ int   h2t[HW];                    // sq horiz dist to target mask
    __shared__ int   h2p[HW];                    // sq horiz dist to pred mask
    __shared__ float s1[NWARP], s2[NWARP];
    __shared__ int   sct[NWARP], scp[NWARP];

    const int bi      = blockIdx.x;
    const int item    = bi >> 2;
    const int quarter = bi & 3;
    const int tid     = threadIdx.x;

    const float* pb = pred   + item * HW;
    const float* tb = target + item * HW;
    const float THR = 0.30001f;

    // --- Load both images once; build both row-mask sets via ballot. ----
    unsigned pmbit = 0, tmbit = 0;
    #pragma unroll
    for (int k = 0; k < 4; k++) {
        const int pix = tid + k * NT;
        float pv = pb[pix];
        float tv = tb[pix];
        bool pmb = (fabsf(pv - 1.0f) <= THR);
        bool tmb = (tv != 0.0f);
        unsigned pbal = __ballot_sync(0xffffffffu, pmb);
        unsigned tbal = __ballot_sync(0xffffffffu, tmb);
        if ((tid & 31) == 0) {
            ((unsigned*)prmask)[pix >> 5] = pbal;
            ((unsigned*)trmask)[pix >> 5] = tbal;
        }
        if (k == quarter) { pmbit = pmb ? 1u : 0u; tmbit = tmb ? 1u : 0u; }
    }
    __syncthreads();   // masks complete

    // --- Phase 1: squared horizontal distances for BOTH masks -----------
    #pragma unroll
    for (int k = 0; k < 4; k++) {
        const int idx = tid + k * NT;
        const int x = idx >> 6, y = idx & 63;
        int ht = bitdist(trmask[x], y);
        int hp = bitdist(prmask[x], y);
        h2t[idx] = ht * ht;
        h2p[idx] = hp * hp;
    }
    __syncthreads();

    // --- Phase 2: one pixel per thread, both distances ------------------
    const int pix = quarter * NT + tid;
    const int x = pix >> 6;
    const int y = pix & 63;
    int dt = h2t[pix];            // r = 0 (own row)
    int dp = h2p[pix];

    // r = 1, 2 unrolled vote-free (unconditional exact min updates)
    #pragma unroll
    for (int r = 1; r <= 2; r++) {
        const int rr = r * r;
        const int xu = x - r, xd = x + r;
        if (xu >= 0) {
            const int off = xu * Wdim + y;
            dt = min(dt, rr + h2t[off]);
            dp = min(dp, rr + h2p[off]);
        }
        if (xd < Wdim) {
            const int off = xd * Wdim + y;
            dt = min(dt, rr + h2t[off]);
            dp = min(dp, rr + h2p[off]);
        }
    }
    // Rare continuation beyond r = 2
    if (__any_sync(0xffffffffu, 9 < max(dt, dp))) {
        #pragma unroll 1
        for (int r = 3; r < Wdim; r++) {
            const int rr = r * r;
            if (!__any_sync(0xffffffffu, rr < max(dt, dp))) break;
            const int xu = x - r, xd = x + r;
            if (xu >= 0) {
                const int off = xu * Wdim + y;
                dt = min(dt, rr + h2t[off]);
                dp = min(dp, rr + h2p[off]);
            }
            if (xd < Wdim) {
                const int off = xd * Wdim + y;
                dt = min(dt, rr + h2t[off]);
                dp = min(dp, rr + h2p[off]);
            }
        }
    }
    float a1 = pmbit ? sqrtf((float)dt) : 0.0f;   // term1: pred px -> target
    float a2 = tmbit ? sqrtf((float)dp) : 0.0f;   // term2: target px -> pred
    int   ct = __reduce_add_sync(0xffffffffu, (int)tmbit);
    int   cp = __reduce_add_sync(0xffffffffu, (int)pmbit);

    // --- Block reduction (32 warps) --------------------------------------
    #pragma unroll
    for (int o = 16; o > 0; o >>= 1) {
        a1 += __shfl_xor_sync(0xffffffffu, a1, o);
        a2 += __shfl_xor_sync(0xffffffffu, a2, o);
    }
    const int wid = tid >> 5, lid = tid & 31;
    if (lid == 0) { s1[wid] = a1; s2[wid] = a2; sct[wid] = ct; scp[wid] = cp; }
    __syncthreads();

    int isLast = 0;
    if (tid == 0) {
        float t1 = 0.0f, t2 = 0.0f; int tC = 0, pC = 0;
        #pragma unroll
        for (int w = 0; w < NWARP; w++) {
            t1 += s1[w]; t2 += s2[w]; tC += sct[w]; pC += scp[w];
        }
        g_t1[bi] = t1; g_t2[bi] = t2; g_ct[bi] = tC; g_cp[bi] = pC;
        __threadfence();
        unsigned old = atomicAdd(&g_done, 1u);
        isLast = (old == 4 * ITEMS - 1) ? 1 : 0;
    }
    // Broadcast within warp 0 only (no extra block barrier; only warp 0
    // finalizes and tid 0 belongs to it).
    if (wid == 0) {
        isLast = __shfl_sync(0xffffffffu, isLast, 0);
        if (isLast) {
            __threadfence();
            volatile float* v1 = g_t1;
            volatile float* v2 = g_t2;
            volatile int*   vt = g_ct;
            volatile int*   vp = g_cp;
            const int i = lid;
            float t1 = v1[4*i] + v1[4*i+1] + v1[4*i+2] + v1[4*i+3];
            float t2 = v2[4*i] + v2[4*i+1] + v2[4*i+2] + v2[4*i+3];
            int   nt = vt[4*i] + vt[4*i+1] + vt[4*i+2] + vt[4*i+3];
            int   np = vp[4*i] + vp[4*i+1] + vp[4*i+2] + vp[4*i+3];
            float v = (nt > 0 && np > 0) ? (t1 + t2) / (2.0f * (float)nt) : 0.0f;
            #pragma unroll
            for (int o = 16; o > 0; o >>= 1)
                v += __shfl_xor_sync(0xffffffffu, v, o);
            if (lid == 0) {
                out[0] = v / (float)ITEMS;
                __threadfence();
                g_done = 0;               // reset for next graph replay
            }
        }
    }
}

extern "C" void kernel_launch(void* const* d_in, const int* in_sizes, int n_in,
                              void* d_out, int out_size)
{
    const float* pred   = (const float*)d_in[0];
    const float* target = (const float*)d_in[1];
    float* out = (float*)d_out;
    (void)in_sizes; (void)n_in; (void)out_size;

    bahl_fused_kernel<<<4 * ITEMS, NT>>>(pred, target, out);
}